// round 12
// baseline (speedup 1.0000x reference)
#include <cuda_runtime.h>
#include <cuda_fp16.h>
#include <math.h>
#include <stdint.h>

#define SQ 4096
#define HID 2048
#define NH 8
#define NKV 4
#define HD 256
#define FFI 8192
#define NQKV 4096   /* 2048 q + 1024 k + 1024 v */

// ================= device scratch =================
__device__ __half g_xn[(size_t)SQ * HID];
__device__ __half g_qkv16[(size_t)SQ * NQKV];
__device__ __half g_qh[(size_t)NH * SQ * HD];
__device__ __half g_kh[(size_t)NKV * SQ * HD];
__device__ __half g_vt[(size_t)NKV * HD * SQ];
__device__ __half g_attn[(size_t)SQ * HID];
__device__ float g_h1[(size_t)SQ * HID];
__device__ __half g_gact[(size_t)SQ * FFI];
// transposed fp16 weights, layout [N, K]
__device__ __half g_qkvw[(size_t)NQKV * HID];
__device__ __half g_ow[(size_t)HID * HID];
__device__ __half g_gw[(size_t)FFI * HID];
__device__ __half g_uw[(size_t)FFI * HID];
__device__ __half g_dw[(size_t)HID * FFI];

// ================= PTX helpers =================
__device__ __forceinline__ uint32_t smem_u32(const void* p) {
    return (uint32_t)__cvta_generic_to_shared(p);
}
__device__ __forceinline__ void cpasync16(uint32_t s, const void* g) {
    asm volatile("cp.async.cg.shared.global [%0], [%1], 16;" :: "r"(s), "l"(g));
}
__device__ __forceinline__ void cp_commit() { asm volatile("cp.async.commit_group;" ::: "memory"); }
template <int N> __device__ __forceinline__ void cp_wait() {
    asm volatile("cp.async.wait_group %0;" :: "n"(N) : "memory");
}
__device__ __forceinline__ void ldsm4(uint32_t* r, uint32_t a) {
    asm volatile("ldmatrix.sync.aligned.m8n8.x4.shared.b16 {%0,%1,%2,%3}, [%4];"
                 : "=r"(r[0]), "=r"(r[1]), "=r"(r[2]), "=r"(r[3]) : "r"(a));
}
__device__ __forceinline__ void ldsm2(uint32_t* r, uint32_t a) {
    asm volatile("ldmatrix.sync.aligned.m8n8.x2.shared.b16 {%0,%1}, [%2];"
                 : "=r"(r[0]), "=r"(r[1]) : "r"(a));
}
__device__ __forceinline__ void mma16816(float* d, const uint32_t* a, const uint32_t* b) {
    asm volatile(
        "mma.sync.aligned.m16n8k16.row.col.f32.f16.f16.f32 "
        "{%0,%1,%2,%3}, {%4,%5,%6,%7}, {%8,%9}, {%0,%1,%2,%3};"
        : "+f"(d[0]), "+f"(d[1]), "+f"(d[2]), "+f"(d[3])
        : "r"(a[0]), "r"(a[1]), "r"(a[2]), "r"(a[3]), "r"(b[0]), "r"(b[1]));
}
__device__ __forceinline__ uint32_t packh2(float a, float b) {
    __half2 h = __floats2half2_rn(a, b);
    return *(uint32_t*)&h;
}
__device__ __forceinline__ float gelu_tanh(float x) {
    float x3 = x * x * x;
    return 0.5f * x * (1.f + tanhf(0.7978845608028654f * (x + 0.044715f * x3)));
}

// ================= fp16 HMMA GEMM: tile 128x128, Kc=64, 3 stages, 1 sync/iter =================
#define KC 64
#define ROWB 144                      /* 64 halves + 8 pad */
#define AB_STAGE (128 * ROWB)         /* 18432 */
#define STAGE_BYTES (2 * AB_STAGE)    /* 36864 */
#define NSTAGE 3
#define GEMM_SMEM (NSTAGE * STAGE_BYTES)  /* 110592 -> 2 CTAs/SM */

__device__ __forceinline__ void gemm_load_chunk(
    uint32_t st, int tid, const __half* gA, const __half* gB, int k0, int K)
{
    #pragma unroll
    for (int rep = 0; rep < 8; rep++) {
        int id = tid + rep * 256;      // 0..2047
        int r = id >> 3;               // 0..255
        int g = id & 7;
        const __half* src = (r < 128) ? (gA + (size_t)r * K + k0 + g * 8)
                                      : (gB + (size_t)(r - 128) * K + k0 + g * 8);
        cpasync16(st + (uint32_t)(r * ROWB + g * 16), src);
    }
    cp_commit();
}

__global__ __launch_bounds__(256) void mma_gemm_kernel(
    const __half* __restrict__ A, const __half* __restrict__ B,
    const float* __restrict__ Cres, float* __restrict__ C,
    __half* __restrict__ Ch, int N, int K)
{
    extern __shared__ __align__(128) char smem[];
    const uint32_t sb = smem_u32(smem);
    const int tid = threadIdx.x;
    const int lane = tid & 31;
    const int wid = tid >> 5;
    const int wm = wid >> 2;
    const int wn = wid & 3;
    const int m0 = blockIdx.x * 128;
    const int n0 = blockIdx.y * 128;

    const __half* gA = A + (size_t)m0 * K;
    const __half* gB = B + (size_t)n0 * K;
    const int nch = K / KC;

    float acc[4][4][4];
    #pragma unroll
    for (int mt = 0; mt < 4; mt++)
        #pragma unroll
        for (int nt = 0; nt < 4; nt++)
            #pragma unroll
            for (int e = 0; e < 4; e++) acc[mt][nt][e] = 0.f;

    // prologue: stages 0,1
    #pragma unroll
    for (int c = 0; c < 2; c++)
        gemm_load_chunk(sb + c * STAGE_BYTES, tid, gA, gB, c * KC, K);

    const uint32_t aOff = (uint32_t)((wm * 64 + (lane & 15)) * ROWB + (lane >> 4) * 16);
    const uint32_t bOff = (uint32_t)(AB_STAGE
        + (wn * 32 + (lane & 7) + ((lane >> 4) & 1) * 8) * ROWB
        + ((lane >> 3) & 1) * 16);

    for (int i = 0; i < nch; i++) {
        cp_wait<1>();          // stage i's group complete (positional: all but newest 1)
        __syncthreads();       // publish loads; also orders prev compute before next load
        int ld = i + 2;
        if (ld < nch)
            gemm_load_chunk(sb + (uint32_t)((ld % NSTAGE) * STAGE_BYTES), tid, gA, gB,
                            ld * KC, K);
        else
            cp_commit();
        uint32_t st = sb + (uint32_t)((i % NSTAGE) * STAGE_BYTES);
        uint32_t aB = st + aOff;
        uint32_t bB = st + bOff;
        #pragma unroll
        for (int ks = 0; ks < 4; ks++) {
            uint32_t ak = aB + ks * 32;
            uint32_t bk = bB + ks * 32;
            uint32_t ah[4][4], bh[2][4];
            #pragma unroll
            for (int mt = 0; mt < 4; mt++) ldsm4(ah[mt], ak + mt * (16 * ROWB));
            #pragma unroll
            for (int np = 0; np < 2; np++) ldsm4(bh[np], bk + np * (16 * ROWB));
            #pragma unroll
            for (int mt = 0; mt < 4; mt++)
                #pragma unroll
                for (int nt = 0; nt < 4; nt++)
                    mma16816(acc[mt][nt], ah[mt], bh[nt >> 1] + (nt & 1) * 2);
        }
    }

    const int rbase = m0 + wm * 64 + (lane >> 2);
    const int cbase = n0 + wn * 32 + (lane & 3) * 2;
    #pragma unroll
    for (int mt = 0; mt < 4; mt++) {
        #pragma unroll
        for (int nt = 0; nt < 4; nt++) {
            int r = rbase + mt * 16;
            int c = cbase + nt * 8;
            if (Ch) {
                *(__half2*)(Ch + (size_t)r * N + c) =
                    __floats2half2_rn(acc[mt][nt][0], acc[mt][nt][1]);
                *(__half2*)(Ch + (size_t)(r + 8) * N + c) =
                    __floats2half2_rn(acc[mt][nt][2], acc[mt][nt][3]);
            } else {
                float2 v0 = make_float2(acc[mt][nt][0], acc[mt][nt][1]);
                float2 v1 = make_float2(acc[mt][nt][2], acc[mt][nt][3]);
                if (Cres) {
                    const float2 r0 = *(const float2*)(Cres + (size_t)r * N + c);
                    const float2 r1 = *(const float2*)(Cres + (size_t)(r + 8) * N + c);
                    v0.x += r0.x; v0.y += r0.y;
                    v1.x += r1.x; v1.y += r1.y;
                }
                *(float2*)(C + (size_t)r * N + c) = v0;
                *(float2*)(C + (size_t)(r + 8) * N + c) = v1;
            }
        }
    }
}

// ================= fused gate||up GEMM + gelu epilogue: 2 stages, 1 sync/iter =================
#define GU_STAGE (3 * AB_STAGE)       /* 55296: A / Bg / Bu */
#define GU_NSTAGE 2
#define GU_SMEM (GU_NSTAGE * GU_STAGE)  /* 110592 -> 2 CTAs/SM */

__device__ __forceinline__ void gu_load_chunk(
    uint32_t st, int tid, const __half* gA, const __half* gBg, const __half* gBu,
    int k0, int K)
{
    #pragma unroll
    for (int rep = 0; rep < 12; rep++) {
        int id = tid + rep * 256;
        int r = id >> 3;               // 0..383
        int g = id & 7;
        const __half* src = (r < 128) ? (gA + (size_t)r * K + k0 + g * 8)
                          : (r < 256) ? (gBg + (size_t)(r - 128) * K + k0 + g * 8)
                                      : (gBu + (size_t)(r - 256) * K + k0 + g * 8);
        cpasync16(st + (uint32_t)(r * ROWB + g * 16), src);
    }
    cp_commit();
}

__global__ __launch_bounds__(256) void gateup_kernel(
    const __half* __restrict__ A, const __half* __restrict__ Bg,
    const __half* __restrict__ Bu, __half* __restrict__ Out, int N, int K)
{
    extern __shared__ __align__(128) char smem[];
    const uint32_t sb = smem_u32(smem);
    const int tid = threadIdx.x;
    const int lane = tid & 31;
    const int wid = tid >> 5;
    const int wm = wid >> 2;
    const int wn = wid & 3;
    const int m0 = blockIdx.x * 128;
    const int n0 = blockIdx.y * 128;

    const __half* gA = A + (size_t)m0 * K;
    const __half* gBg = Bg + (size_t)n0 * K;
    const __half* gBu = Bu + (size_t)n0 * K;
    const int nch = K / KC;

    float accG[4][4][4], accU[4][4][4];
    #pragma unroll
    for (int mt = 0; mt < 4; mt++)
        #pragma unroll
        for (int nt = 0; nt < 4; nt++)
            #pragma unroll
            for (int e = 0; e < 4; e++) { accG[mt][nt][e] = 0.f; accU[mt][nt][e] = 0.f; }

    gu_load_chunk(sb, tid, gA, gBg, gBu, 0, K);   // stage 0

    const uint32_t aOff = (uint32_t)((wm * 64 + (lane & 15)) * ROWB + (lane >> 4) * 16);
    const uint32_t bRow = (uint32_t)((wn * 32 + (lane & 7) + ((lane >> 4) & 1) * 8) * ROWB
                                     + ((lane >> 3) & 1) * 16);

    for (int i = 0; i < nch; i++) {
        cp_wait<0>();
        __syncthreads();
        if (i + 1 < nch)
            gu_load_chunk(sb + (uint32_t)(((i + 1) & 1) * GU_STAGE), tid, gA, gBg, gBu,
                          (i + 1) * KC, K);
        else
            cp_commit();
        uint32_t st = sb + (uint32_t)((i & 1) * GU_STAGE);
        uint32_t aB = st + aOff;
        uint32_t gB_ = st + AB_STAGE + bRow;
        uint32_t uB = st + 2 * AB_STAGE + bRow;
        #pragma unroll
        for (int ks = 0; ks < 4; ks++) {
            uint32_t ak = aB + ks * 32;
            uint32_t ah[4][4], bg[2][4], bu[2][4];
            #pragma unroll
            for (int mt = 0; mt < 4; mt++) ldsm4(ah[mt], ak + mt * (16 * ROWB));
            #pragma unroll
            for (int np = 0; np < 2; np++) {
                ldsm4(bg[np], gB_ + np * (16 * ROWB) + ks * 32);
                ldsm4(bu[np], uB + np * (16 * ROWB) + ks * 32);
            }
            #pragma unroll
            for (int mt = 0; mt < 4; mt++)
                #pragma unroll
                for (int nt = 0; nt < 4; nt++) {
                    mma16816(accG[mt][nt], ah[mt], bg[nt >> 1] + (nt & 1) * 2);
                    mma16816(accU[mt][nt], ah[mt], bu[nt >> 1] + (nt & 1) * 2);
                }
        }
    }

    const int rbase = m0 + wm * 64 + (lane >> 2);
    const int cbase = n0 + wn * 32 + (lane & 3) * 2;
    #pragma unroll
    for (int mt = 0; mt < 4; mt++) {
        #pragma unroll
        for (int nt = 0; nt < 4; nt++) {
            int r = rbase + mt * 16;
            int c = cbase + nt * 8;
            *(__half2*)(Out + (size_t)r * N + c) = __floats2half2_rn(
                gelu_tanh(accG[mt][nt][0]) * accU[mt][nt][0],
                gelu_tanh(accG[mt][nt][1]) * accU[mt][nt][1]);
            *(__half2*)(Out + (size_t)(r + 8) * N + c) = __floats2half2_rn(
                gelu_tanh(accG[mt][nt][2]) * accU[mt][nt][2],
                gelu_tanh(accG[mt][nt][3]) * accU[mt][nt][3]);
        }
    }
}

// ================= weight transpose: W[K,N] fp32 -> T[N,K] fp16 =================
__global__ __launch_bounds__(256) void wconv_kernel(
    const float* __restrict__ W, __half* __restrict__ T, int K, int N)
{
    __shared__ float t[32][33];
    int n0 = blockIdx.x * 32, k0 = blockIdx.y * 32;
    int tid = threadIdx.x;
    int tn = tid & 31, tk = tid >> 5;
    #pragma unroll
    for (int i = 0; i < 4; i++)
        t[tk + 8 * i][tn] = W[(size_t)(k0 + tk + 8 * i) * N + n0 + tn];
    __syncthreads();
    #pragma unroll
    for (int i = 0; i < 4; i++) {
        int r = tk + 8 * i, c = tn;
        T[(size_t)(n0 + r) * K + k0 + c] = __float2half(t[c][r]);
    }
}

// ================= V transpose =================
__global__ __launch_bounds__(256) void vtrans_kernel() {
    __shared__ __half t[32][40];
    int s0 = blockIdx.x * 32, d0 = blockIdx.y * 32;
    int kvh = blockIdx.z;
    int tid = threadIdx.x;
    int tx = tid & 31, ty = tid >> 5;
    #pragma unroll
    for (int i = 0; i < 4; i++)
        t[ty + 8 * i][tx] =
            g_qkv16[(size_t)(s0 + ty + 8 * i) * NQKV + 3072 + kvh * HD + d0 + tx];
    __syncthreads();
    #pragma unroll
    for (int i = 0; i < 4; i++) {
        int d = ty + 8 * i, s = tx;
        g_vt[(size_t)kvh * HD * SQ + (size_t)(d0 + d) * SQ + s0 + s] = t[s][d];
    }
}

// ================= RMSNorm -> fp16 =================
__device__ __forceinline__ float warp_red_sum(float v) {
    #pragma unroll
    for (int o = 16; o > 0; o >>= 1) v += __shfl_xor_sync(0xffffffffu, v, o);
    return v;
}

__global__ void rmsnorm_kernel(const float* __restrict__ x, const float* __restrict__ w,
                               __half* __restrict__ out) {
    int row = blockIdx.x;
    int tid = threadIdx.x;
    const float* xr = x + (size_t)row * HID;
    float s = 0.f;
    for (int i = tid; i < HID; i += 256) { float v = xr[i]; s += v * v; }
    __shared__ float red[8];
    __shared__ float s_inv;
    s = warp_red_sum(s);
    if ((tid & 31) == 0) red[tid >> 5] = s;
    __syncthreads();
    if (tid == 0) {
        float t = 0.f;
        #pragma unroll
        for (int i = 0; i < 8; i++) t += red[i];
        s_inv = rsqrtf(t / (float)HID + 1e-6f);
    }
    __syncthreads();
    float inv = s_inv;
    __half* orow = out + (size_t)row * HID;
    for (int i = tid * 2; i < HID; i += 512) {
        float v0 = xr[i] * inv * w[i];
        float v1 = xr[i + 1] * inv * w[i + 1];
        *(__half2*)(orow + i) = __floats2half2_rn(v0, v1);
    }
}

// ================= RoPE =================
__global__ void rope_kernel(const int* __restrict__ pos_ids) {
    int idx = blockIdx.x * 256 + threadIdx.x;
    if (idx >= SQ * 128) return;
    int j = idx & 127;
    int s = idx >> 7;
    float inv = (float)(1.0 / pow(10000.0, (double)j / 128.0));
    float angf = (float)pos_ids[s] * inv;
    double ang = (double)angf;
    float c = (float)cos(ang);
    float sn = (float)sin(ang);
    #pragma unroll
    for (int h = 0; h < NH; h++) {
        const __half* b = g_qkv16 + (size_t)s * NQKV + h * HD;
        float x0 = __half2float(b[j]), x1 = __half2float(b[j + 128]);
        __half* o = g_qh + ((size_t)h * SQ + s) * HD;
        o[j]       = __float2half((x0 * c - x1 * sn) * 0.0625f);
        o[j + 128] = __float2half((x1 * c + x0 * sn) * 0.0625f);
    }
    #pragma unroll
    for (int h = 0; h < NKV; h++) {
        const __half* b = g_qkv16 + (size_t)s * NQKV + 2048 + h * HD;
        float x0 = __half2float(b[j]), x1 = __half2float(b[j + 128]);
        __half* o = g_kh + ((size_t)h * SQ + s) * HD;
        o[j]       = __float2half(x0 * c - x1 * sn);
        o[j + 128] = __float2half(x1 * c + x0 * sn);
    }
}

// ================= fp16 HMMA flash attention, double-buffered, 1 sync/tile =================
#define ABM 128
#define ABN 64
#define QROWH 264
#define VROWH 72
#define KSTAGE (ABN * QROWH * 2)              /* 33792 */
#define VSTAGE (HD * VROWH * 2)               /* 36864 */
#define ASM_K (ABM * QROWH * 2)               /* 67584 */
#define ASM_V (ASM_K + 2 * KSTAGE)            /* 135168 */
#define ASM_MK (ASM_V + 2 * VSTAGE)           /* 208896 */
#define ATTN_SMEM (ASM_MK + 2 * ABN * 4)      /* 209408 */

__global__ __launch_bounds__(256, 1) void attn_mma_kernel(const int* __restrict__ amask) {
    extern __shared__ __align__(128) char asmem[];
    const uint32_t sb = smem_u32(asmem);
    const int tid = threadIdx.x;
    const int lane = tid & 31;
    const int w = tid >> 5;
    const int bx = gridDim.x - 1 - blockIdx.x;   // longest CTAs first
    const int h = blockIdx.y;
    const int kvh = h >> 1;
    const int m0 = bx * ABM;
    const int wrow = w * 16;
    const int rq = lane >> 2;
    const int q2 = (lane & 3) * 2;

    const __half* gQ = g_qh + ((size_t)h * SQ + m0) * HD;
    const __half* gK = g_kh + (size_t)kvh * SQ * HD;
    const __half* gVt = g_vt + (size_t)kvh * HD * SQ;

    // Q tile (persistent)
    for (int c = tid; c < ABM * 32; c += 256) {
        int r = c >> 5, g = c & 31;
        cpasync16(sb + (uint32_t)(r * (QROWH * 2) + g * 16),
                  (const char*)(gQ + (size_t)r * HD) + g * 16);
    }
    cp_commit();

    float accO[32][4];
    #pragma unroll
    for (int vt = 0; vt < 32; vt++)
        #pragma unroll
        for (int e = 0; e < 4; e++) accO[vt][e] = 0.f;
    float mprev0 = -1e30f, mprev1 = -1e30f;
    float lsum0 = 0.f, lsum1 = 0.f;

    const uint32_t aQ = sb + (uint32_t)((wrow + (lane & 15)) * (QROWH * 2) + ((lane >> 4) * 8) * 2);
    const uint32_t bKoff = (uint32_t)((lane & 7) * (QROWH * 2) + (((lane >> 3) & 1) * 8) * 2);
    const uint32_t bVoff = (uint32_t)((lane & 7) * (VROWH * 2) + (((lane >> 3) & 1) * 8) * 2);

    const int ntiles = 2 * bx + 2;

    // prefetch tile 0 into buffer 0
    {
        for (int c = tid; c < ABN * 32; c += 256) {
            int r = c >> 5, g = c & 31;
            cpasync16(sb + (uint32_t)(ASM_K + r * (QROWH * 2) + g * 16),
                      (const char*)(gK + (size_t)r * HD) + g * 16);
        }
        for (int c = tid; c < HD * 8; c += 256) {
            int r = c >> 3, g = c & 7;
            cpasync16(sb + (uint32_t)(ASM_V + r * (VROWH * 2) + g * 16),
                      (const char*)(gVt + (size_t)r * SQ) + g * 16);
        }
        if (tid < ABN) ((float*)(asmem + ASM_MK))[tid] = (amask[tid] > 0) ? 0.f : -1e30f;
        cp_commit();
    }

    for (int jt = 0; jt < ntiles; jt++) {
        const int cur = jt & 1;
        cp_wait<0>();       // current tile (and Q) resident in this thread's view
        __syncthreads();    // publish to all warps; order prev compute before next load
        if (jt + 1 < ntiles) {
            const int nxt = (jt + 1) & 1;
            const int n1 = (jt + 1) * ABN;
            for (int c = tid; c < ABN * 32; c += 256) {
                int r = c >> 5, g = c & 31;
                cpasync16(sb + (uint32_t)(ASM_K + nxt * KSTAGE + r * (QROWH * 2) + g * 16),
                          (const char*)(gK + (size_t)(n1 + r) * HD) + g * 16);
            }
            for (int c = tid; c < HD * 8; c += 256) {
                int r = c >> 3, g = c & 7;
                cpasync16(sb + (uint32_t)(ASM_V + nxt * VSTAGE + r * (VROWH * 2) + g * 16),
                          (const char*)(gVt + (size_t)r * SQ + n1) + g * 16);
            }
            if (tid < ABN)
                ((float*)(asmem + ASM_MK))[nxt * ABN + tid] =
                    (amask[n1 + tid] > 0) ? 0.f : -1e30f;
            cp_commit();
        } else {
            cp_commit();
        }

        const int n0 = jt * ABN;
        if (n0 <= m0 + wrow + 15) {
            const float* mk = (const float*)(asmem + ASM_MK) + cur * ABN;
            const uint32_t bK = sb + (uint32_t)(ASM_K + cur * KSTAGE) + bKoff;
            const uint32_t bV = sb + (uint32_t)(ASM_V + cur * VSTAGE) + bVoff;

            float accS[8][4];
            #pragma unroll
            for (int nt = 0; nt < 8; nt++)
                #pragma unroll
                for (int e = 0; e < 4; e++) accS[nt][e] = 0.f;
            #pragma unroll
            for (int kc = 0; kc < 16; kc++) {
                uint32_t a[4];
                ldsm4(a, aQ + kc * 32);
                #pragma unroll
                for (int nt = 0; nt < 8; nt++) {
                    uint32_t b[2];
                    ldsm2(b, bK + nt * (8 * QROWH * 2) + kc * 32);
                    mma16816(accS[nt], a, b);
                }
            }

            const int grow0 = m0 + wrow + rq;
            const int grow1 = grow0 + 8;
            #pragma unroll
            for (int nt = 0; nt < 8; nt++) {
                int c0 = nt * 8 + q2;
                float k0m = mk[c0], k1m = mk[c0 + 1];
                int gc0 = n0 + c0, gc1 = gc0 + 1;
                accS[nt][0] = (gc0 > grow0) ? -1e30f : accS[nt][0] + k0m;
                accS[nt][1] = (gc1 > grow0) ? -1e30f : accS[nt][1] + k1m;
                accS[nt][2] = (gc0 > grow1) ? -1e30f : accS[nt][2] + k0m;
                accS[nt][3] = (gc1 > grow1) ? -1e30f : accS[nt][3] + k1m;
            }

            float mx0 = -1e30f, mx1 = -1e30f;
            #pragma unroll
            for (int nt = 0; nt < 8; nt++) {
                mx0 = fmaxf(mx0, fmaxf(accS[nt][0], accS[nt][1]));
                mx1 = fmaxf(mx1, fmaxf(accS[nt][2], accS[nt][3]));
            }
            mx0 = fmaxf(mx0, __shfl_xor_sync(0xffffffffu, mx0, 1));
            mx0 = fmaxf(mx0, __shfl_xor_sync(0xffffffffu, mx0, 2));
            mx1 = fmaxf(mx1, __shfl_xor_sync(0xffffffffu, mx1, 1));
            mx1 = fmaxf(mx1, __shfl_xor_sync(0xffffffffu, mx1, 2));
            float nm0 = fmaxf(mprev0, mx0);
            float nm1 = fmaxf(mprev1, mx1);
            float sc0 = __expf(mprev0 - nm0);
            float sc1 = __expf(mprev1 - nm1);
            float s0 = 0.f, s1 = 0.f;
            #pragma unroll
            for (int nt = 0; nt < 8; nt++) {
                float p0 = __expf(accS[nt][0] - nm0);
                float p1 = __expf(accS[nt][1] - nm0);
                float p2 = __expf(accS[nt][2] - nm1);
                float p3 = __expf(accS[nt][3] - nm1);
                accS[nt][0] = p0; accS[nt][1] = p1; accS[nt][2] = p2; accS[nt][3] = p3;
                s0 += p0 + p1; s1 += p2 + p3;
            }
            s0 += __shfl_xor_sync(0xffffffffu, s0, 1);
            s0 += __shfl_xor_sync(0xffffffffu, s0, 2);
            s1 += __shfl_xor_sync(0xffffffffu, s1, 1);
            s1 += __shfl_xor_sync(0xffffffffu, s1, 2);
            lsum0 = lsum0 * sc0 + s0;
            lsum1 = lsum1 * sc1 + s1;
            mprev0 = nm0; mprev1 = nm1;
            #pragma unroll
            for (int vt = 0; vt < 32; vt++) {
                accO[vt][0] *= sc0; accO[vt][1] *= sc0;
                accO[vt][2] *= sc1; accO[vt][3] *= sc1;
            }

            #pragma unroll
            for (int kc2 = 0; kc2 < 4; kc2++) {
                uint32_t a[4];
                a[0] = packh2(accS[2 * kc2][0], accS[2 * kc2][1]);
                a[1] = packh2(accS[2 * kc2][2], accS[2 * kc2][3]);
                a[2] = packh2(accS[2 * kc2 + 1][0], accS[2 * kc2 + 1][1]);
                a[3] = packh2(accS[2 * kc2 + 1][2], accS[2 * kc2 + 1][3]);
                #pragma unroll
                for (int vt = 0; vt < 32; vt++) {
                    uint32_t b[2];
                    ldsm2(b, bV + vt * (8 * VROWH * 2) + kc2 * 32);
                    mma16816(accO[vt], a, b);
                }
            }
        }
    }

    float il0 = 1.f / lsum0;
    float il1 = 1.f / lsum1;
    __half* o0 = g_attn + (size_t)(m0 + wrow + rq) * HID + h * HD;
    __half* o1 = g_attn + (size_t)(m0 + wrow + rq + 8) * HID + h * HD;
    #pragma unroll
    for (int vt = 0; vt < 32; vt++) {
        int c = vt * 8 + q2;
        *(__half2*)(o0 + c) = __floats2half2_rn(accO[vt][0] * il0, accO[vt][1] * il0);
        *(__half2*)(o1 + c) = __floats2half2_rn(accO[vt][2] * il1, accO[vt][3] * il1);
    }
}

// ================= launch =================
template <typename T>
static T* symaddr(const void* sym) {
    void* p = nullptr;
    cudaGetSymbolAddress(&p, sym);
    return (T*)p;
}

extern "C" void kernel_launch(void* const* d_in, const int* in_sizes, int n_in,
                              void* d_out, int out_size) {
    (void)in_sizes; (void)n_in; (void)out_size;
    const float* hs     = (const float*)d_in[0];
    const float* q_w    = (const float*)d_in[1];
    const float* k_w    = (const float*)d_in[2];
    const float* v_w    = (const float*)d_in[3];
    const float* o_w    = (const float*)d_in[4];
    const float* gate_w = (const float*)d_in[5];
    const float* up_w   = (const float*)d_in[6];
    const float* down_w = (const float*)d_in[7];
    const float* ln1_w  = (const float*)d_in[8];
    const float* ln2_w  = (const float*)d_in[9];
    const int*   amask  = (const int*)d_in[10];
    const int*   pos    = (const int*)d_in[11];
    float* out = (float*)d_out;

    __half* xn = symaddr<__half>(g_xn);
    __half* qkv16 = symaddr<__half>(g_qkv16);
    __half* at = symaddr<__half>(g_attn);
    float* h1 = symaddr<float>(g_h1);
    __half* ga = symaddr<__half>(g_gact);
    __half* qkvw = symaddr<__half>(g_qkvw);
    __half* ow = symaddr<__half>(g_ow);
    __half* gw = symaddr<__half>(g_gw);
    __half* uw = symaddr<__half>(g_uw);
    __half* dw = symaddr<__half>(g_dw);

    cudaFuncSetAttribute(mma_gemm_kernel, cudaFuncAttributeMaxDynamicSharedMemorySize, GEMM_SMEM);
    cudaFuncSetAttribute(gateup_kernel, cudaFuncAttributeMaxDynamicSharedMemorySize, GU_SMEM);
    cudaFuncSetAttribute(attn_mma_kernel, cudaFuncAttributeMaxDynamicSharedMemorySize, ATTN_SMEM);

    // 0) weight transpose -> fp16 [N,K]; q/k/v concatenated
    wconv_kernel<<<dim3(HID / 32, HID / 32), 256>>>(q_w, qkvw, HID, HID);
    wconv_kernel<<<dim3((NKV * HD) / 32, HID / 32), 256>>>(
        k_w, qkvw + (size_t)2048 * HID, HID, NKV * HD);
    wconv_kernel<<<dim3((NKV * HD) / 32, HID / 32), 256>>>(
        v_w, qkvw + (size_t)3072 * HID, HID, NKV * HD);
    wconv_kernel<<<dim3(HID / 32, HID / 32), 256>>>(o_w, ow, HID, HID);
    wconv_kernel<<<dim3(FFI / 32, HID / 32), 256>>>(gate_w, gw, HID, FFI);
    wconv_kernel<<<dim3(FFI / 32, HID / 32), 256>>>(up_w, uw, HID, FFI);
    wconv_kernel<<<dim3(HID / 32, FFI / 32), 256>>>(down_w, dw, FFI, HID);

    // 1) input RMSNorm -> fp16
    rmsnorm_kernel<<<SQ, 256>>>(hs, ln1_w, xn);

    // 2) fused QKV projection (fp16 out)
    mma_gemm_kernel<<<dim3(SQ / 128, NQKV / 128), 256, GEMM_SMEM>>>(
        xn, qkvw, nullptr, nullptr, qkv16, NQKV, HID);

    // 3) RoPE + V transpose
    rope_kernel<<<(SQ * 128 + 255) / 256, 256>>>(pos);
    vtrans_kernel<<<dim3(SQ / 32, HD / 32, NKV), 256>>>();

    // 4) flash attention (double-buffered, 1 sync/tile)
    attn_mma_kernel<<<dim3(SQ / ABM, NH), 256, ATTN_SMEM>>>(amask);

    // 5) O projection + residual (fp32 out)
    mma_gemm_kernel<<<dim3(SQ / 128, HID / 128), 256, GEMM_SMEM>>>(
        at, ow, hs, h1, nullptr, HID, HID);

    // 6) post-attn RMSNorm -> fp16
    rmsnorm_kernel<<<SQ, 256>>>(h1, ln2_w, xn);

    // 7) MLP
    gateup_kernel<<<dim3(SQ / 128, FFI / 128), 256, GU_SMEM>>>(xn, gw, uw, ga, FFI, HID);
    mma_gemm_kernel<<<dim3(SQ / 128, HID / 128), 256, GEMM_SMEM>>>(
        ga, dw, h1, out, nullptr, HID, FFI);
}

// round 13
// speedup vs baseline: 1.4859x; 1.4859x over previous
#include <cuda_runtime.h>
#include <cuda_fp16.h>
#include <math.h>
#include <stdint.h>

#define SQ 4096
#define HID 2048
#define NH 8
#define NKV 4
#define HD 256
#define FFI 8192
#define NQKV 4096   /* 2048 q + 1024 k + 1024 v */

// ================= device scratch =================
__device__ __half g_xn[(size_t)SQ * HID];
__device__ __half g_qkv16[(size_t)SQ * NQKV];
__device__ __half g_qh[(size_t)NH * SQ * HD];
__device__ __half g_kh[(size_t)NKV * SQ * HD];
__device__ __half g_vt[(size_t)NKV * HD * SQ];
__device__ __half g_attn[(size_t)SQ * HID];
__device__ float g_h1[(size_t)SQ * HID];
__device__ __half g_gact[(size_t)SQ * FFI];
// transposed fp16 weights, layout [N, K]
__device__ __half g_qkvw[(size_t)NQKV * HID];
__device__ __half g_ow[(size_t)HID * HID];
__device__ __half g_gw[(size_t)FFI * HID];
__device__ __half g_uw[(size_t)FFI * HID];
__device__ __half g_dw[(size_t)HID * FFI];

// ================= PTX helpers =================
__device__ __forceinline__ uint32_t smem_u32(const void* p) {
    return (uint32_t)__cvta_generic_to_shared(p);
}
__device__ __forceinline__ void cpasync16(uint32_t s, const void* g) {
    asm volatile("cp.async.cg.shared.global [%0], [%1], 16;" :: "r"(s), "l"(g));
}
__device__ __forceinline__ void cp_commit() { asm volatile("cp.async.commit_group;" ::: "memory"); }
template <int N> __device__ __forceinline__ void cp_wait() {
    asm volatile("cp.async.wait_group %0;" :: "n"(N) : "memory");
}
__device__ __forceinline__ void ldsm4(uint32_t* r, uint32_t a) {
    asm volatile("ldmatrix.sync.aligned.m8n8.x4.shared.b16 {%0,%1,%2,%3}, [%4];"
                 : "=r"(r[0]), "=r"(r[1]), "=r"(r[2]), "=r"(r[3]) : "r"(a));
}
__device__ __forceinline__ void ldsm2(uint32_t* r, uint32_t a) {
    asm volatile("ldmatrix.sync.aligned.m8n8.x2.shared.b16 {%0,%1}, [%2];"
                 : "=r"(r[0]), "=r"(r[1]) : "r"(a));
}
__device__ __forceinline__ void mma16816(float* d, const uint32_t* a, const uint32_t* b) {
    asm volatile(
        "mma.sync.aligned.m16n8k16.row.col.f32.f16.f16.f32 "
        "{%0,%1,%2,%3}, {%4,%5,%6,%7}, {%8,%9}, {%0,%1,%2,%3};"
        : "+f"(d[0]), "+f"(d[1]), "+f"(d[2]), "+f"(d[3])
        : "r"(a[0]), "r"(a[1]), "r"(a[2]), "r"(a[3]), "r"(b[0]), "r"(b[1]));
}
__device__ __forceinline__ uint32_t packh2(float a, float b) {
    __half2 h = __floats2half2_rn(a, b);
    return *(uint32_t*)&h;
}
__device__ __forceinline__ float gelu_tanh(float x) {
    float x3 = x * x * x;
    return 0.5f * x * (1.f + tanhf(0.7978845608028654f * (x + 0.044715f * x3)));
}

// ================= fp16 HMMA GEMM: tile 128x128, Kc=64, 3 stages (R9 structure) =================
#define KC 64
#define ROWB 144                      /* 64 halves + 8 pad */
#define AB_STAGE (128 * ROWB)         /* 18432 */
#define STAGE_BYTES (2 * AB_STAGE)    /* 36864: A rows 0-127, B rows 128-255 */
#define NSTAGE 3
#define GEMM_SMEM (NSTAGE * STAGE_BYTES)   /* 110592 -> 2 CTAs/SM */

__device__ __forceinline__ void gemm_load_chunk(
    uint32_t st, int tid, const __half* gA, const __half* gB, int k0, int K)
{
    #pragma unroll
    for (int rep = 0; rep < 8; rep++) {
        int id = tid + rep * 256;      // 0..2047
        int r = id >> 3;               // 0..255
        int g = id & 7;                // 16B group within 128B row
        const __half* src = (r < 128) ? (gA + (size_t)r * K + k0 + g * 8)
                                      : (gB + (size_t)(r - 128) * K + k0 + g * 8);
        cpasync16(st + (uint32_t)(r * ROWB + g * 16), src);
    }
    cp_commit();
}

__global__ __launch_bounds__(256) void mma_gemm_kernel(
    const __half* __restrict__ A, const __half* __restrict__ B,
    const float* __restrict__ Cres, float* __restrict__ C,
    __half* __restrict__ Ch, int N, int K)
{
    extern __shared__ __align__(128) char smem[];
    const uint32_t sb = smem_u32(smem);
    const int tid = threadIdx.x;
    const int lane = tid & 31;
    const int wid = tid >> 5;
    const int wm = wid >> 2;
    const int wn = wid & 3;
    const int m0 = blockIdx.x * 128;
    const int n0 = blockIdx.y * 128;

    const __half* gA = A + (size_t)m0 * K;
    const __half* gB = B + (size_t)n0 * K;
    const int nch = K / KC;

    float acc[4][4][4];
    #pragma unroll
    for (int mt = 0; mt < 4; mt++)
        #pragma unroll
        for (int nt = 0; nt < 4; nt++)
            #pragma unroll
            for (int e = 0; e < 4; e++) acc[mt][nt][e] = 0.f;

    #pragma unroll
    for (int c = 0; c < NSTAGE; c++)
        gemm_load_chunk(sb + c * STAGE_BYTES, tid, gA, gB, c * KC, K);

    const uint32_t aOff = (uint32_t)((wm * 64 + (lane & 15)) * ROWB + (lane >> 4) * 16);
    const uint32_t bOff = (uint32_t)(AB_STAGE
        + (wn * 32 + (lane & 7) + ((lane >> 4) & 1) * 8) * ROWB
        + ((lane >> 3) & 1) * 16);

    for (int i = 0; i < nch; i++) {
        cp_wait<NSTAGE - 1>();
        __syncthreads();
        uint32_t st = sb + (uint32_t)((i % NSTAGE) * STAGE_BYTES);
        uint32_t aB = st + aOff;
        uint32_t bB = st + bOff;
        #pragma unroll
        for (int ks = 0; ks < 4; ks++) {
            uint32_t ak = aB + ks * 32;
            uint32_t bk = bB + ks * 32;
            uint32_t ah[4][4], bh[2][4];
            #pragma unroll
            for (int mt = 0; mt < 4; mt++) ldsm4(ah[mt], ak + mt * (16 * ROWB));
            #pragma unroll
            for (int np = 0; np < 2; np++) ldsm4(bh[np], bk + np * (16 * ROWB));
            #pragma unroll
            for (int mt = 0; mt < 4; mt++)
                #pragma unroll
                for (int nt = 0; nt < 4; nt++)
                    mma16816(acc[mt][nt], ah[mt], bh[nt >> 1] + (nt & 1) * 2);
        }
        __syncthreads();
        if (i + NSTAGE < nch)
            gemm_load_chunk(st, tid, gA, gB, (i + NSTAGE) * KC, K);
        else
            cp_commit();
    }

    const int rbase = m0 + wm * 64 + (lane >> 2);
    const int cbase = n0 + wn * 32 + (lane & 3) * 2;
    #pragma unroll
    for (int mt = 0; mt < 4; mt++) {
        #pragma unroll
        for (int nt = 0; nt < 4; nt++) {
            int r = rbase + mt * 16;
            int c = cbase + nt * 8;
            if (Ch) {
                *(__half2*)(Ch + (size_t)r * N + c) =
                    __floats2half2_rn(acc[mt][nt][0], acc[mt][nt][1]);
                *(__half2*)(Ch + (size_t)(r + 8) * N + c) =
                    __floats2half2_rn(acc[mt][nt][2], acc[mt][nt][3]);
            } else {
                float2 v0 = make_float2(acc[mt][nt][0], acc[mt][nt][1]);
                float2 v1 = make_float2(acc[mt][nt][2], acc[mt][nt][3]);
                if (Cres) {
                    const float2 r0 = *(const float2*)(Cres + (size_t)r * N + c);
                    const float2 r1 = *(const float2*)(Cres + (size_t)(r + 8) * N + c);
                    v0.x += r0.x; v0.y += r0.y;
                    v1.x += r1.x; v1.y += r1.y;
                }
                *(float2*)(C + (size_t)r * N + c) = v0;
                *(float2*)(C + (size_t)(r + 8) * N + c) = v1;
            }
        }
    }
}

// ================= fused gate||up GEMM + gelu epilogue (R9 structure, 3 stages) =================
#define GU_STAGE (3 * AB_STAGE)       /* A rows 0-127, Bg 128-255, Bu 256-383 */
#define GU_NSTAGE 3
#define GU_SMEM (GU_NSTAGE * GU_STAGE)

__device__ __forceinline__ void gu_load_chunk(
    uint32_t st, int tid, const __half* gA, const __half* gBg, const __half* gBu,
    int k0, int K)
{
    #pragma unroll
    for (int rep = 0; rep < 12; rep++) {
        int id = tid + rep * 256;      // 0..3071
        int r = id >> 3;               // 0..383
        int g = id & 7;
        const __half* src = (r < 128) ? (gA + (size_t)r * K + k0 + g * 8)
                          : (r < 256) ? (gBg + (size_t)(r - 128) * K + k0 + g * 8)
                                      : (gBu + (size_t)(r - 256) * K + k0 + g * 8);
        cpasync16(st + (uint32_t)(r * ROWB + g * 16), src);
    }
    cp_commit();
}

__global__ __launch_bounds__(256) void gateup_kernel(
    const __half* __restrict__ A, const __half* __restrict__ Bg,
    const __half* __restrict__ Bu, __half* __restrict__ Out, int N, int K)
{
    extern __shared__ __align__(128) char smem[];
    const uint32_t sb = smem_u32(smem);
    const int tid = threadIdx.x;
    const int lane = tid & 31;
    const int wid = tid >> 5;
    const int wm = wid >> 2;
    const int wn = wid & 3;
    const int m0 = blockIdx.x * 128;
    const int n0 = blockIdx.y * 128;

    const __half* gA = A + (size_t)m0 * K;
    const __half* gBg = Bg + (size_t)n0 * K;
    const __half* gBu = Bu + (size_t)n0 * K;
    const int nch = K / KC;

    float accG[4][4][4], accU[4][4][4];
    #pragma unroll
    for (int mt = 0; mt < 4; mt++)
        #pragma unroll
        for (int nt = 0; nt < 4; nt++)
            #pragma unroll
            for (int e = 0; e < 4; e++) { accG[mt][nt][e] = 0.f; accU[mt][nt][e] = 0.f; }

    #pragma unroll
    for (int c = 0; c < GU_NSTAGE; c++)
        gu_load_chunk(sb + c * GU_STAGE, tid, gA, gBg, gBu, c * KC, K);

    const uint32_t aOff = (uint32_t)((wm * 64 + (lane & 15)) * ROWB + (lane >> 4) * 16);
    const uint32_t bRow = (uint32_t)((wn * 32 + (lane & 7) + ((lane >> 4) & 1) * 8) * ROWB
                                     + ((lane >> 3) & 1) * 16);

    for (int i = 0; i < nch; i++) {
        cp_wait<GU_NSTAGE - 1>();
        __syncthreads();
        uint32_t st = sb + (uint32_t)((i % GU_NSTAGE) * GU_STAGE);
        uint32_t aB = st + aOff;
        uint32_t gB_ = st + AB_STAGE + bRow;
        uint32_t uB = st + 2 * AB_STAGE + bRow;
        #pragma unroll
        for (int ks = 0; ks < 4; ks++) {
            uint32_t ak = aB + ks * 32;
            uint32_t ah[4][4], bg[2][4], bu[2][4];
            #pragma unroll
            for (int mt = 0; mt < 4; mt++) ldsm4(ah[mt], ak + mt * (16 * ROWB));
            #pragma unroll
            for (int np = 0; np < 2; np++) {
                ldsm4(bg[np], gB_ + np * (16 * ROWB) + ks * 32);
                ldsm4(bu[np], uB + np * (16 * ROWB) + ks * 32);
            }
            #pragma unroll
            for (int mt = 0; mt < 4; mt++)
                #pragma unroll
                for (int nt = 0; nt < 4; nt++) {
                    mma16816(accG[mt][nt], ah[mt], bg[nt >> 1] + (nt & 1) * 2);
                    mma16816(accU[mt][nt], ah[mt], bu[nt >> 1] + (nt & 1) * 2);
                }
        }
        __syncthreads();
        if (i + GU_NSTAGE < nch)
            gu_load_chunk(st, tid, gA, gBg, gBu, (i + GU_NSTAGE) * KC, K);
        else
            cp_commit();
    }

    const int rbase = m0 + wm * 64 + (lane >> 2);
    const int cbase = n0 + wn * 32 + (lane & 3) * 2;
    #pragma unroll
    for (int mt = 0; mt < 4; mt++) {
        #pragma unroll
        for (int nt = 0; nt < 4; nt++) {
            int r = rbase + mt * 16;
            int c = cbase + nt * 8;
            *(__half2*)(Out + (size_t)r * N + c) = __floats2half2_rn(
                gelu_tanh(accG[mt][nt][0]) * accU[mt][nt][0],
                gelu_tanh(accG[mt][nt][1]) * accU[mt][nt][1]);
            *(__half2*)(Out + (size_t)(r + 8) * N + c) = __floats2half2_rn(
                gelu_tanh(accG[mt][nt][2]) * accU[mt][nt][2],
                gelu_tanh(accG[mt][nt][3]) * accU[mt][nt][3]);
        }
    }
}

// ================= weight transpose: W[K,N] fp32 -> T[N,K] fp16 =================
__global__ __launch_bounds__(256) void wconv_kernel(
    const float* __restrict__ W, __half* __restrict__ T, int K, int N)
{
    __shared__ float t[32][33];
    int n0 = blockIdx.x * 32, k0 = blockIdx.y * 32;
    int tid = threadIdx.x;
    int tn = tid & 31, tk = tid >> 5;
    #pragma unroll
    for (int i = 0; i < 4; i++)
        t[tk + 8 * i][tn] = W[(size_t)(k0 + tk + 8 * i) * N + n0 + tn];
    __syncthreads();
    #pragma unroll
    for (int i = 0; i < 4; i++) {
        int r = tk + 8 * i, c = tn;
        T[(size_t)(n0 + r) * K + k0 + c] = __float2half(t[c][r]);
    }
}

// ================= V transpose =================
__global__ __launch_bounds__(256) void vtrans_kernel() {
    __shared__ __half t[32][40];
    int s0 = blockIdx.x * 32, d0 = blockIdx.y * 32;
    int kvh = blockIdx.z;
    int tid = threadIdx.x;
    int tx = tid & 31, ty = tid >> 5;
    #pragma unroll
    for (int i = 0; i < 4; i++)
        t[ty + 8 * i][tx] =
            g_qkv16[(size_t)(s0 + ty + 8 * i) * NQKV + 3072 + kvh * HD + d0 + tx];
    __syncthreads();
    #pragma unroll
    for (int i = 0; i < 4; i++) {
        int d = ty + 8 * i, s = tx;
        g_vt[(size_t)kvh * HD * SQ + (size_t)(d0 + d) * SQ + s0 + s] = t[s][d];
    }
}

// ================= RMSNorm -> fp16 =================
__device__ __forceinline__ float warp_red_sum(float v) {
    #pragma unroll
    for (int o = 16; o > 0; o >>= 1) v += __shfl_xor_sync(0xffffffffu, v, o);
    return v;
}

__global__ void rmsnorm_kernel(const float* __restrict__ x, const float* __restrict__ w,
                               __half* __restrict__ out) {
    int row = blockIdx.x;
    int tid = threadIdx.x;
    const float* xr = x + (size_t)row * HID;
    float s = 0.f;
    for (int i = tid; i < HID; i += 256) { float v = xr[i]; s += v * v; }
    __shared__ float red[8];
    __shared__ float s_inv;
    s = warp_red_sum(s);
    if ((tid & 31) == 0) red[tid >> 5] = s;
    __syncthreads();
    if (tid == 0) {
        float t = 0.f;
        #pragma unroll
        for (int i = 0; i < 8; i++) t += red[i];
        s_inv = rsqrtf(t / (float)HID + 1e-6f);
    }
    __syncthreads();
    float inv = s_inv;
    __half* orow = out + (size_t)row * HID;
    for (int i = tid * 2; i < HID; i += 512) {
        float v0 = xr[i] * inv * w[i];
        float v1 = xr[i + 1] * inv * w[i + 1];
        *(__half2*)(orow + i) = __floats2half2_rn(v0, v1);
    }
}

// ================= RoPE =================
__global__ void rope_kernel(const int* __restrict__ pos_ids) {
    int idx = blockIdx.x * 256 + threadIdx.x;
    if (idx >= SQ * 128) return;
    int j = idx & 127;
    int s = idx >> 7;
    float inv = (float)(1.0 / pow(10000.0, (double)j / 128.0));
    float angf = (float)pos_ids[s] * inv;
    double ang = (double)angf;
    float c = (float)cos(ang);
    float sn = (float)sin(ang);
    #pragma unroll
    for (int h = 0; h < NH; h++) {
        const __half* b = g_qkv16 + (size_t)s * NQKV + h * HD;
        float x0 = __half2float(b[j]), x1 = __half2float(b[j + 128]);
        __half* o = g_qh + ((size_t)h * SQ + s) * HD;
        o[j]       = __float2half((x0 * c - x1 * sn) * 0.0625f);
        o[j + 128] = __float2half((x1 * c + x0 * sn) * 0.0625f);
    }
    #pragma unroll
    for (int h = 0; h < NKV; h++) {
        const __half* b = g_qkv16 + (size_t)s * NQKV + 2048 + h * HD;
        float x0 = __half2float(b[j]), x1 = __half2float(b[j + 128]);
        __half* o = g_kh + ((size_t)h * SQ + s) * HD;
        o[j]       = __float2half(x0 * c - x1 * sn);
        o[j + 128] = __float2half(x1 * c + x0 * sn);
    }
}

// ================= fp16 HMMA flash attention, double-buffered K/V (R11 structure) =================
#define ABM 128
#define ABN 64
#define QROWH 264
#define VROWH 72
#define KSTAGE (ABN * QROWH * 2)              /* 33792 */
#define VSTAGE (HD * VROWH * 2)               /* 36864 */
#define ASM_K (ABM * QROWH * 2)               /* 67584 */
#define ASM_V (ASM_K + 2 * KSTAGE)            /* 135168 */
#define ASM_MK (ASM_V + 2 * VSTAGE)           /* 208896 */
#define ATTN_SMEM (ASM_MK + 2 * ABN * 4)      /* 209408 */

__global__ __launch_bounds__(256, 1) void attn_mma_kernel(const int* __restrict__ amask) {
    extern __shared__ __align__(128) char asmem[];
    const uint32_t sb = smem_u32(asmem);
    const int tid = threadIdx.x;
    const int lane = tid & 31;
    const int w = tid >> 5;
    const int bx = gridDim.x - 1 - blockIdx.x;   // longest CTAs first
    const int h = blockIdx.y;
    const int kvh = h >> 1;
    const int m0 = bx * ABM;
    const int wrow = w * 16;
    const int rq = lane >> 2;
    const int q2 = (lane & 3) * 2;

    const __half* gQ = g_qh + ((size_t)h * SQ + m0) * HD;
    const __half* gK = g_kh + (size_t)kvh * SQ * HD;
    const __half* gVt = g_vt + (size_t)kvh * HD * SQ;

    // Q tile (persistent)
    for (int c = tid; c < ABM * 32; c += 256) {
        int r = c >> 5, g = c & 31;
        cpasync16(sb + (uint32_t)(r * (QROWH * 2) + g * 16),
                  (const char*)(gQ + (size_t)r * HD) + g * 16);
    }
    cp_commit();

    float accO[32][4];
    #pragma unroll
    for (int vt = 0; vt < 32; vt++)
        #pragma unroll
        for (int e = 0; e < 4; e++) accO[vt][e] = 0.f;
    float mprev0 = -1e30f, mprev1 = -1e30f;
    float lsum0 = 0.f, lsum1 = 0.f;

    const uint32_t aQ = sb + (uint32_t)((wrow + (lane & 15)) * (QROWH * 2) + ((lane >> 4) * 8) * 2);
    const uint32_t bKoff = (uint32_t)((lane & 7) * (QROWH * 2) + (((lane >> 3) & 1) * 8) * 2);
    const uint32_t bVoff = (uint32_t)((lane & 7) * (VROWH * 2) + (((lane >> 3) & 1) * 8) * 2);

    const int ntiles = 2 * bx + 2;

    // prefetch tile 0 into buffer 0
    {
        for (int c = tid; c < ABN * 32; c += 256) {
            int r = c >> 5, g = c & 31;
            cpasync16(sb + (uint32_t)(ASM_K + r * (QROWH * 2) + g * 16),
                      (const char*)(gK + (size_t)r * HD) + g * 16);
        }
        for (int c = tid; c < HD * 8; c += 256) {
            int r = c >> 3, g = c & 7;
            cpasync16(sb + (uint32_t)(ASM_V + r * (VROWH * 2) + g * 16),
                      (const char*)(gVt + (size_t)r * SQ) + g * 16);
        }
        if (tid < ABN) ((float*)(asmem + ASM_MK))[tid] = (amask[tid] > 0) ? 0.f : -1e30f;
        cp_commit();
    }

    for (int jt = 0; jt < ntiles; jt++) {
        const int cur = jt & 1;
        if (jt + 1 < ntiles) {
            const int nxt = (jt + 1) & 1;
            const int n1 = (jt + 1) * ABN;
            for (int c = tid; c < ABN * 32; c += 256) {
                int r = c >> 5, g = c & 31;
                cpasync16(sb + (uint32_t)(ASM_K + nxt * KSTAGE + r * (QROWH * 2) + g * 16),
                          (const char*)(gK + (size_t)(n1 + r) * HD) + g * 16);
            }
            for (int c = tid; c < HD * 8; c += 256) {
                int r = c >> 3, g = c & 7;
                cpasync16(sb + (uint32_t)(ASM_V + nxt * VSTAGE + r * (VROWH * 2) + g * 16),
                          (const char*)(gVt + (size_t)r * SQ + n1) + g * 16);
            }
            if (tid < ABN)
                ((float*)(asmem + ASM_MK))[nxt * ABN + tid] =
                    (amask[n1 + tid] > 0) ? 0.f : -1e30f;
            cp_commit();
            cp_wait<1>();
        } else {
            cp_wait<0>();
        }
        __syncthreads();

        const int n0 = jt * ABN;
        if (n0 <= m0 + wrow + 15) {
            const float* mk = (const float*)(asmem + ASM_MK) + cur * ABN;
            const uint32_t bK = sb + (uint32_t)(ASM_K + cur * KSTAGE) + bKoff;
            const uint32_t bV = sb + (uint32_t)(ASM_V + cur * VSTAGE) + bVoff;

            float accS[8][4];
            #pragma unroll
            for (int nt = 0; nt < 8; nt++)
                #pragma unroll
                for (int e = 0; e < 4; e++) accS[nt][e] = 0.f;
            #pragma unroll
            for (int kc = 0; kc < 16; kc++) {
                uint32_t a[4];
                ldsm4(a, aQ + kc * 32);
                #pragma unroll
                for (int nt = 0; nt < 8; nt++) {
                    uint32_t b[2];
                    ldsm2(b, bK + nt * (8 * QROWH * 2) + kc * 32);
                    mma16816(accS[nt], a, b);
                }
            }

            const int grow0 = m0 + wrow + rq;
            const int grow1 = grow0 + 8;
            #pragma unroll
            for (int nt = 0; nt < 8; nt++) {
                int c0 = nt * 8 + q2;
                float k0m = mk[c0], k1m = mk[c0 + 1];
                int gc0 = n0 + c0, gc1 = gc0 + 1;
                accS[nt][0] = (gc0 > grow0) ? -1e30f : accS[nt][0] + k0m;
                accS[nt][1] = (gc1 > grow0) ? -1e30f : accS[nt][1] + k1m;
                accS[nt][2] = (gc0 > grow1) ? -1e30f : accS[nt][2] + k0m;
                accS[nt][3] = (gc1 > grow1) ? -1e30f : accS[nt][3] + k1m;
            }

            float mx0 = -1e30f, mx1 = -1e30f;
            #pragma unroll
            for (int nt = 0; nt < 8; nt++) {
                mx0 = fmaxf(mx0, fmaxf(accS[nt][0], accS[nt][1]));
                mx1 = fmaxf(mx1, fmaxf(accS[nt][2], accS[nt][3]));
            }
            mx0 = fmaxf(mx0, __shfl_xor_sync(0xffffffffu, mx0, 1));
            mx0 = fmaxf(mx0, __shfl_xor_sync(0xffffffffu, mx0, 2));
            mx1 = fmaxf(mx1, __shfl_xor_sync(0xffffffffu, mx1, 1));
            mx1 = fmaxf(mx1, __shfl_xor_sync(0xffffffffu, mx1, 2));
            float nm0 = fmaxf(mprev0, mx0);
            float nm1 = fmaxf(mprev1, mx1);
            float sc0 = __expf(mprev0 - nm0);
            float sc1 = __expf(mprev1 - nm1);
            float s0 = 0.f, s1 = 0.f;
            #pragma unroll
            for (int nt = 0; nt < 8; nt++) {
                float p0 = __expf(accS[nt][0] - nm0);
                float p1 = __expf(accS[nt][1] - nm0);
                float p2 = __expf(accS[nt][2] - nm1);
                float p3 = __expf(accS[nt][3] - nm1);
                accS[nt][0] = p0; accS[nt][1] = p1; accS[nt][2] = p2; accS[nt][3] = p3;
                s0 += p0 + p1; s1 += p2 + p3;
            }
            s0 += __shfl_xor_sync(0xffffffffu, s0, 1);
            s0 += __shfl_xor_sync(0xffffffffu, s0, 2);
            s1 += __shfl_xor_sync(0xffffffffu, s1, 1);
            s1 += __shfl_xor_sync(0xffffffffu, s1, 2);
            lsum0 = lsum0 * sc0 + s0;
            lsum1 = lsum1 * sc1 + s1;
            mprev0 = nm0; mprev1 = nm1;
            #pragma unroll
            for (int vt = 0; vt < 32; vt++) {
                accO[vt][0] *= sc0; accO[vt][1] *= sc0;
                accO[vt][2] *= sc1; accO[vt][3] *= sc1;
            }

            #pragma unroll
            for (int kc2 = 0; kc2 < 4; kc2++) {
                uint32_t a[4];
                a[0] = packh2(accS[2 * kc2][0], accS[2 * kc2][1]);
                a[1] = packh2(accS[2 * kc2][2], accS[2 * kc2][3]);
                a[2] = packh2(accS[2 * kc2 + 1][0], accS[2 * kc2 + 1][1]);
                a[3] = packh2(accS[2 * kc2 + 1][2], accS[2 * kc2 + 1][3]);
                #pragma unroll
                for (int vt = 0; vt < 32; vt++) {
                    uint32_t b[2];
                    ldsm2(b, bV + vt * (8 * VROWH * 2) + kc2 * 32);
                    mma16816(accO[vt], a, b);
                }
            }
        }
        __syncthreads();   // all warps done with buffer `cur` before refill next iter
    }

    float il0 = 1.f / lsum0;
    float il1 = 1.f / lsum1;
    __half* o0 = g_attn + (size_t)(m0 + wrow + rq) * HID + h * HD;
    __half* o1 = g_attn + (size_t)(m0 + wrow + rq + 8) * HID + h * HD;
    #pragma unroll
    for (int vt = 0; vt < 32; vt++) {
        int c = vt * 8 + q2;
        *(__half2*)(o0 + c) = __floats2half2_rn(accO[vt][0] * il0, accO[vt][1] * il0);
        *(__half2*)(o1 + c) = __floats2half2_rn(accO[vt][2] * il1, accO[vt][3] * il1);
    }
}

// ================= launch =================
template <typename T>
static T* symaddr(const void* sym) {
    void* p = nullptr;
    cudaGetSymbolAddress(&p, sym);
    return (T*)p;
}

extern "C" void kernel_launch(void* const* d_in, const int* in_sizes, int n_in,
                              void* d_out, int out_size) {
    (void)in_sizes; (void)n_in; (void)out_size;
    const float* hs     = (const float*)d_in[0];
    const float* q_w    = (const float*)d_in[1];
    const float* k_w    = (const float*)d_in[2];
    const float* v_w    = (const float*)d_in[3];
    const float* o_w    = (const float*)d_in[4];
    const float* gate_w = (const float*)d_in[5];
    const float* up_w   = (const float*)d_in[6];
    const float* down_w = (const float*)d_in[7];
    const float* ln1_w  = (const float*)d_in[8];
    const float* ln2_w  = (const float*)d_in[9];
    const int*   amask  = (const int*)d_in[10];
    const int*   pos    = (const int*)d_in[11];
    float* out = (float*)d_out;

    __half* xn = symaddr<__half>(g_xn);
    __half* qkv16 = symaddr<__half>(g_qkv16);
    __half* at = symaddr<__half>(g_attn);
    float* h1 = symaddr<float>(g_h1);
    __half* ga = symaddr<__half>(g_gact);
    __half* qkvw = symaddr<__half>(g_qkvw);
    __half* ow = symaddr<__half>(g_ow);
    __half* gw = symaddr<__half>(g_gw);
    __half* uw = symaddr<__half>(g_uw);
    __half* dw = symaddr<__half>(g_dw);

    cudaFuncSetAttribute(mma_gemm_kernel, cudaFuncAttributeMaxDynamicSharedMemorySize, GEMM_SMEM);
    cudaFuncSetAttribute(gateup_kernel, cudaFuncAttributeMaxDynamicSharedMemorySize, GU_SMEM);
    cudaFuncSetAttribute(attn_mma_kernel, cudaFuncAttributeMaxDynamicSharedMemorySize, ATTN_SMEM);

    // 0) weight transpose -> fp16 [N,K]; q/k/v concatenated
    wconv_kernel<<<dim3(HID / 32, HID / 32), 256>>>(q_w, qkvw, HID, HID);
    wconv_kernel<<<dim3((NKV * HD) / 32, HID / 32), 256>>>(
        k_w, qkvw + (size_t)2048 * HID, HID, NKV * HD);
    wconv_kernel<<<dim3((NKV * HD) / 32, HID / 32), 256>>>(
        v_w, qkvw + (size_t)3072 * HID, HID, NKV * HD);
    wconv_kernel<<<dim3(HID / 32, HID / 32), 256>>>(o_w, ow, HID, HID);
    wconv_kernel<<<dim3(FFI / 32, HID / 32), 256>>>(gate_w, gw, HID, FFI);
    wconv_kernel<<<dim3(FFI / 32, HID / 32), 256>>>(up_w, uw, HID, FFI);
    wconv_kernel<<<dim3(HID / 32, FFI / 32), 256>>>(down_w, dw, FFI, HID);

    // 1) input RMSNorm -> fp16
    rmsnorm_kernel<<<SQ, 256>>>(hs, ln1_w, xn);

    // 2) fused QKV projection (fp16 out)
    mma_gemm_kernel<<<dim3(SQ / 128, NQKV / 128), 256, GEMM_SMEM>>>(
        xn, qkvw, nullptr, nullptr, qkv16, NQKV, HID);

    // 3) RoPE + V transpose
    rope_kernel<<<(SQ * 128 + 255) / 256, 256>>>(pos);
    vtrans_kernel<<<dim3(SQ / 32, HD / 32, NKV), 256>>>();

    // 4) flash attention (double-buffered)
    attn_mma_kernel<<<dim3(SQ / ABM, NH), 256, ATTN_SMEM>>>(amask);

    // 5) O projection + residual (fp32 out)
    mma_gemm_kernel<<<dim3(SQ / 128, HID / 128), 256, GEMM_SMEM>>>(
        at, ow, hs, h1, nullptr, HID, HID);

    // 6) post-attn RMSNorm -> fp16
    rmsnorm_kernel<<<SQ, 256>>>(h1, ln2_w, xn);

    // 7) MLP
    gateup_kernel<<<dim3(SQ / 128, FFI / 128), 256, GU_SMEM>>>(xn, gw, uw, ga, FFI, HID);
    mma_gemm_kernel<<<dim3(SQ / 128, HID / 128), 256, GEMM_SMEM>>>(
        ga, dw, h1, out, nullptr, HID, FFI);
}

// round 14
// speedup vs baseline: 1.5012x; 1.0103x over previous
#include <cuda_runtime.h>
#include <cuda_fp16.h>
#include <math.h>
#include <stdint.h>

#define SQ 4096
#define HID 2048
#define NH 8
#define NKV 4
#define HD 256
#define FFI 8192
#define NQKV 4096   /* 2048 q + 1024 k + 1024 v */

// ================= device scratch =================
__device__ __half g_xn[(size_t)SQ * HID];
__device__ __half g_qkv16[(size_t)SQ * NQKV];
__device__ __half g_qh[(size_t)NH * SQ * HD];
__device__ __half g_kh[(size_t)NKV * SQ * HD];
__device__ __half g_vt[(size_t)NKV * HD * SQ];
__device__ __half g_attn[(size_t)SQ * HID];
__device__ float g_h1[(size_t)SQ * HID];
__device__ __half g_gact[(size_t)SQ * FFI];
// transposed fp16 weights, layout [N, K]
__device__ __half g_qkvw[(size_t)NQKV * HID];
__device__ __half g_ow[(size_t)HID * HID];
__device__ __half g_gw[(size_t)FFI * HID];
__device__ __half g_uw[(size_t)FFI * HID];
__device__ __half g_dw[(size_t)HID * FFI];

// ================= PTX helpers =================
__device__ __forceinline__ uint32_t smem_u32(const void* p) {
    return (uint32_t)__cvta_generic_to_shared(p);
}
__device__ __forceinline__ void cpasync16(uint32_t s, const void* g) {
    asm volatile("cp.async.cg.shared.global [%0], [%1], 16;" :: "r"(s), "l"(g));
}
__device__ __forceinline__ void cp_commit() { asm volatile("cp.async.commit_group;" ::: "memory"); }
template <int N> __device__ __forceinline__ void cp_wait() {
    asm volatile("cp.async.wait_group %0;" :: "n"(N) : "memory");
}
__device__ __forceinline__ void ldsm4(uint32_t* r, uint32_t a) {
    asm volatile("ldmatrix.sync.aligned.m8n8.x4.shared.b16 {%0,%1,%2,%3}, [%4];"
                 : "=r"(r[0]), "=r"(r[1]), "=r"(r[2]), "=r"(r[3]) : "r"(a));
}
__device__ __forceinline__ void ldsm2(uint32_t* r, uint32_t a) {
    asm volatile("ldmatrix.sync.aligned.m8n8.x2.shared.b16 {%0,%1}, [%2];"
                 : "=r"(r[0]), "=r"(r[1]) : "r"(a));
}
__device__ __forceinline__ void mma16816(float* d, const uint32_t* a, const uint32_t* b) {
    asm volatile(
        "mma.sync.aligned.m16n8k16.row.col.f32.f16.f16.f32 "
        "{%0,%1,%2,%3}, {%4,%5,%6,%7}, {%8,%9}, {%0,%1,%2,%3};"
        : "+f"(d[0]), "+f"(d[1]), "+f"(d[2]), "+f"(d[3])
        : "r"(a[0]), "r"(a[1]), "r"(a[2]), "r"(a[3]), "r"(b[0]), "r"(b[1]));
}
__device__ __forceinline__ uint32_t packh2(float a, float b) {
    __half2 h = __floats2half2_rn(a, b);
    return *(uint32_t*)&h;
}
__device__ __forceinline__ float gelu_tanh(float x) {
    float x3 = x * x * x;
    return 0.5f * x * (1.f + tanhf(0.7978845608028654f * (x + 0.044715f * x3)));
}

// ================= fp16 HMMA GEMM: tile 128x128, Kc=64, 3 stages (R9/R13) =================
#define KC 64
#define ROWB 144
#define AB_STAGE (128 * ROWB)
#define STAGE_BYTES (2 * AB_STAGE)
#define NSTAGE 3
#define GEMM_SMEM (NSTAGE * STAGE_BYTES)   /* 110592 -> 2 CTAs/SM */

__device__ __forceinline__ void gemm_load_chunk(
    uint32_t st, int tid, const __half* gA, const __half* gB, int k0, int K)
{
    #pragma unroll
    for (int rep = 0; rep < 8; rep++) {
        int id = tid + rep * 256;
        int r = id >> 3;
        int g = id & 7;
        const __half* src = (r < 128) ? (gA + (size_t)r * K + k0 + g * 8)
                                      : (gB + (size_t)(r - 128) * K + k0 + g * 8);
        cpasync16(st + (uint32_t)(r * ROWB + g * 16), src);
    }
    cp_commit();
}

__global__ __launch_bounds__(256) void mma_gemm_kernel(
    const __half* __restrict__ A, const __half* __restrict__ B,
    const float* __restrict__ Cres, float* __restrict__ C,
    __half* __restrict__ Ch, int N, int K)
{
    extern __shared__ __align__(128) char smem[];
    const uint32_t sb = smem_u32(smem);
    const int tid = threadIdx.x;
    const int lane = tid & 31;
    const int wid = tid >> 5;
    const int wm = wid >> 2;
    const int wn = wid & 3;
    const int m0 = blockIdx.x * 128;
    const int n0 = blockIdx.y * 128;

    const __half* gA = A + (size_t)m0 * K;
    const __half* gB = B + (size_t)n0 * K;
    const int nch = K / KC;

    float acc[4][4][4];
    #pragma unroll
    for (int mt = 0; mt < 4; mt++)
        #pragma unroll
        for (int nt = 0; nt < 4; nt++)
            #pragma unroll
            for (int e = 0; e < 4; e++) acc[mt][nt][e] = 0.f;

    #pragma unroll
    for (int c = 0; c < NSTAGE; c++)
        gemm_load_chunk(sb + c * STAGE_BYTES, tid, gA, gB, c * KC, K);

    const uint32_t aOff = (uint32_t)((wm * 64 + (lane & 15)) * ROWB + (lane >> 4) * 16);
    const uint32_t bOff = (uint32_t)(AB_STAGE
        + (wn * 32 + (lane & 7) + ((lane >> 4) & 1) * 8) * ROWB
        + ((lane >> 3) & 1) * 16);

    for (int i = 0; i < nch; i++) {
        cp_wait<NSTAGE - 1>();
        __syncthreads();
        uint32_t st = sb + (uint32_t)((i % NSTAGE) * STAGE_BYTES);
        uint32_t aB = st + aOff;
        uint32_t bB = st + bOff;
        #pragma unroll
        for (int ks = 0; ks < 4; ks++) {
            uint32_t ak = aB + ks * 32;
            uint32_t bk = bB + ks * 32;
            uint32_t ah[4][4], bh[2][4];
            #pragma unroll
            for (int mt = 0; mt < 4; mt++) ldsm4(ah[mt], ak + mt * (16 * ROWB));
            #pragma unroll
            for (int np = 0; np < 2; np++) ldsm4(bh[np], bk + np * (16 * ROWB));
            #pragma unroll
            for (int mt = 0; mt < 4; mt++)
                #pragma unroll
                for (int nt = 0; nt < 4; nt++)
                    mma16816(acc[mt][nt], ah[mt], bh[nt >> 1] + (nt & 1) * 2);
        }
        __syncthreads();
        if (i + NSTAGE < nch)
            gemm_load_chunk(st, tid, gA, gB, (i + NSTAGE) * KC, K);
        else
            cp_commit();
    }

    const int rbase = m0 + wm * 64 + (lane >> 2);
    const int cbase = n0 + wn * 32 + (lane & 3) * 2;
    #pragma unroll
    for (int mt = 0; mt < 4; mt++) {
        #pragma unroll
        for (int nt = 0; nt < 4; nt++) {
            int r = rbase + mt * 16;
            int c = cbase + nt * 8;
            if (Ch) {
                *(__half2*)(Ch + (size_t)r * N + c) =
                    __floats2half2_rn(acc[mt][nt][0], acc[mt][nt][1]);
                *(__half2*)(Ch + (size_t)(r + 8) * N + c) =
                    __floats2half2_rn(acc[mt][nt][2], acc[mt][nt][3]);
            } else {
                float2 v0 = make_float2(acc[mt][nt][0], acc[mt][nt][1]);
                float2 v1 = make_float2(acc[mt][nt][2], acc[mt][nt][3]);
                if (Cres) {
                    const float2 r0 = *(const float2*)(Cres + (size_t)r * N + c);
                    const float2 r1 = *(const float2*)(Cres + (size_t)(r + 8) * N + c);
                    v0.x += r0.x; v0.y += r0.y;
                    v1.x += r1.x; v1.y += r1.y;
                }
                *(float2*)(C + (size_t)r * N + c) = v0;
                *(float2*)(C + (size_t)(r + 8) * N + c) = v1;
            }
        }
    }
}

// ================= fused gate||up GEMM + gelu epilogue (R9/R13, 3 stages) =================
#define GU_STAGE (3 * AB_STAGE)
#define GU_NSTAGE 3
#define GU_SMEM (GU_NSTAGE * GU_STAGE)

__device__ __forceinline__ void gu_load_chunk(
    uint32_t st, int tid, const __half* gA, const __half* gBg, const __half* gBu,
    int k0, int K)
{
    #pragma unroll
    for (int rep = 0; rep < 12; rep++) {
        int id = tid + rep * 256;
        int r = id >> 3;
        int g = id & 7;
        const __half* src = (r < 128) ? (gA + (size_t)r * K + k0 + g * 8)
                          : (r < 256) ? (gBg + (size_t)(r - 128) * K + k0 + g * 8)
                                      : (gBu + (size_t)(r - 256) * K + k0 + g * 8);
        cpasync16(st + (uint32_t)(r * ROWB + g * 16), src);
    }
    cp_commit();
}

__global__ __launch_bounds__(256) void gateup_kernel(
    const __half* __restrict__ A, const __half* __restrict__ Bg,
    const __half* __restrict__ Bu, __half* __restrict__ Out, int N, int K)
{
    extern __shared__ __align__(128) char smem[];
    const uint32_t sb = smem_u32(smem);
    const int tid = threadIdx.x;
    const int lane = tid & 31;
    const int wid = tid >> 5;
    const int wm = wid >> 2;
    const int wn = wid & 3;
    const int m0 = blockIdx.x * 128;
    const int n0 = blockIdx.y * 128;

    const __half* gA = A + (size_t)m0 * K;
    const __half* gBg = Bg + (size_t)n0 * K;
    const __half* gBu = Bu + (size_t)n0 * K;
    const int nch = K / KC;

    float accG[4][4][4], accU[4][4][4];
    #pragma unroll
    for (int mt = 0; mt < 4; mt++)
        #pragma unroll
        for (int nt = 0; nt < 4; nt++)
            #pragma unroll
            for (int e = 0; e < 4; e++) { accG[mt][nt][e] = 0.f; accU[mt][nt][e] = 0.f; }

    #pragma unroll
    for (int c = 0; c < GU_NSTAGE; c++)
        gu_load_chunk(sb + c * GU_STAGE, tid, gA, gBg, gBu, c * KC, K);

    const uint32_t aOff = (uint32_t)((wm * 64 + (lane & 15)) * ROWB + (lane >> 4) * 16);
    const uint32_t bRow = (uint32_t)((wn * 32 + (lane & 7) + ((lane >> 4) & 1) * 8) * ROWB
                                     + ((lane >> 3) & 1) * 16);

    for (int i = 0; i < nch; i++) {
        cp_wait<GU_NSTAGE - 1>();
        __syncthreads();
        uint32_t st = sb + (uint32_t)((i % GU_NSTAGE) * GU_STAGE);
        uint32_t aB = st + aOff;
        uint32_t gB_ = st + AB_STAGE + bRow;
        uint32_t uB = st + 2 * AB_STAGE + bRow;
        #pragma unroll
        for (int ks = 0; ks < 4; ks++) {
            uint32_t ak = aB + ks * 32;
            uint32_t ah[4][4], bg[2][4], bu[2][4];
            #pragma unroll
            for (int mt = 0; mt < 4; mt++) ldsm4(ah[mt], ak + mt * (16 * ROWB));
            #pragma unroll
            for (int np = 0; np < 2; np++) {
                ldsm4(bg[np], gB_ + np * (16 * ROWB) + ks * 32);
                ldsm4(bu[np], uB + np * (16 * ROWB) + ks * 32);
            }
            #pragma unroll
            for (int mt = 0; mt < 4; mt++)
                #pragma unroll
                for (int nt = 0; nt < 4; nt++) {
                    mma16816(accG[mt][nt], ah[mt], bg[nt >> 1] + (nt & 1) * 2);
                    mma16816(accU[mt][nt], ah[mt], bu[nt >> 1] + (nt & 1) * 2);
                }
        }
        __syncthreads();
        if (i + GU_NSTAGE < nch)
            gu_load_chunk(st, tid, gA, gBg, gBu, (i + GU_NSTAGE) * KC, K);
        else
            cp_commit();
    }

    const int rbase = m0 + wm * 64 + (lane >> 2);
    const int cbase = n0 + wn * 32 + (lane & 3) * 2;
    #pragma unroll
    for (int mt = 0; mt < 4; mt++) {
        #pragma unroll
        for (int nt = 0; nt < 4; nt++) {
            int r = rbase + mt * 16;
            int c = cbase + nt * 8;
            *(__half2*)(Out + (size_t)r * N + c) = __floats2half2_rn(
                gelu_tanh(accG[mt][nt][0]) * accU[mt][nt][0],
                gelu_tanh(accG[mt][nt][1]) * accU[mt][nt][1]);
            *(__half2*)(Out + (size_t)(r + 8) * N + c) = __floats2half2_rn(
                gelu_tanh(accG[mt][nt][2]) * accU[mt][nt][2],
                gelu_tanh(accG[mt][nt][3]) * accU[mt][nt][3]);
        }
    }
}

// ================= batched weight transpose: 7 jobs, one launch =================
// Each tile: 64x64, float4 loads, fp16 stores (32B/thread contiguous).
struct WJobs {
    const float* W[7];
    __half* T[7];
    int K[7];
    int N[7];
    int ntilesX[7];
    int tileOff[8];
};

__global__ __launch_bounds__(256) void wconv_all_kernel(WJobs jb) {
    __shared__ float t[64][68];
    int bid = blockIdx.x;
    int j = 0;
    #pragma unroll
    for (int i = 1; i < 7; i++) j += (bid >= jb.tileOff[i]) ? 1 : 0;
    int local = bid - jb.tileOff[j];
    int nx = jb.ntilesX[j];
    int n0 = (local % nx) * 64;
    int k0 = (local / nx) * 64;
    const float* W = jb.W[j];
    __half* T = jb.T[j];
    int K = jb.K[j], N = jb.N[j];
    int tid = threadIdx.x;

    // load 64x64 fp32 tile (float4)
    int r = tid >> 2, q = tid & 3;
    #pragma unroll
    for (int i = 0; i < 4; i++) {
        float4 v = *(const float4*)(W + (size_t)(k0 + r) * N + n0 + q * 16 + i * 4);
        *(float4*)&t[r][q * 16 + i * 4] = v;
    }
    __syncthreads();

    // store transposed: thread handles out-row n (= tid&63), 16 k-cols
    int n = tid & 63, qk = tid >> 6;
    __align__(16) __half hbuf[16];
    #pragma unroll
    for (int i = 0; i < 16; i++) hbuf[i] = __float2half(t[qk * 16 + i][n]);
    __half* dst = T + (size_t)(n0 + n) * K + k0 + qk * 16;
    *(uint4*)dst = *(uint4*)&hbuf[0];
    *((uint4*)dst + 1) = *(uint4*)&hbuf[8];
}

// ================= RMSNorm -> fp16 (float4) =================
__device__ __forceinline__ float warp_red_sum(float v) {
    #pragma unroll
    for (int o = 16; o > 0; o >>= 1) v += __shfl_xor_sync(0xffffffffu, v, o);
    return v;
}

__global__ void rmsnorm_kernel(const float* __restrict__ x, const float* __restrict__ w,
                               __half* __restrict__ out) {
    int row = blockIdx.x;
    int tid = threadIdx.x;
    const float* xr = x + (size_t)row * HID;
    float s = 0.f;
    #pragma unroll
    for (int i = 0; i < 2; i++) {
        float4 v = *(const float4*)(xr + tid * 4 + i * 1024);
        s += v.x * v.x + v.y * v.y + v.z * v.z + v.w * v.w;
    }
    __shared__ float red[8];
    __shared__ float s_inv;
    s = warp_red_sum(s);
    if ((tid & 31) == 0) red[tid >> 5] = s;
    __syncthreads();
    if (tid == 0) {
        float tsum = 0.f;
        #pragma unroll
        for (int i = 0; i < 8; i++) tsum += red[i];
        s_inv = rsqrtf(tsum / (float)HID + 1e-6f);
    }
    __syncthreads();
    float inv = s_inv;
    __half* orow = out + (size_t)row * HID;
    #pragma unroll
    for (int i = 0; i < 2; i++) {
        int idx = tid * 4 + i * 1024;
        float4 v = *(const float4*)(xr + idx);
        float4 ww = *(const float4*)(w + idx);
        *(__half2*)(orow + idx)     = __floats2half2_rn(v.x * inv * ww.x, v.y * inv * ww.y);
        *(__half2*)(orow + idx + 2) = __floats2half2_rn(v.z * inv * ww.z, v.w * inv * ww.w);
    }
}

// ================= merged RoPE + V transpose (one launch) =================
__global__ __launch_bounds__(256) void rope_vtrans_kernel(const int* __restrict__ pos_ids) {
    if (blockIdx.x < 2048) {
        // ---- RoPE part: blocks 0..2047, thread = (s, j) ----
        int idx = blockIdx.x * 256 + threadIdx.x;
        int j = idx & 127;
        int s = idx >> 7;
        float inv = (float)(1.0 / pow(10000.0, (double)j / 128.0));
        float angf = (float)pos_ids[s] * inv;
        double ang = (double)angf;
        float c = (float)cos(ang);
        float sn = (float)sin(ang);
        #pragma unroll
        for (int h = 0; h < NH; h++) {
            const __half* b = g_qkv16 + (size_t)s * NQKV + h * HD;
            float x0 = __half2float(b[j]), x1 = __half2float(b[j + 128]);
            __half* o = g_qh + ((size_t)h * SQ + s) * HD;
            o[j]       = __float2half((x0 * c - x1 * sn) * 0.0625f);
            o[j + 128] = __float2half((x1 * c + x0 * sn) * 0.0625f);
        }
        #pragma unroll
        for (int h = 0; h < NKV; h++) {
            const __half* b = g_qkv16 + (size_t)s * NQKV + 2048 + h * HD;
            float x0 = __half2float(b[j]), x1 = __half2float(b[j + 128]);
            __half* o = g_kh + ((size_t)h * SQ + s) * HD;
            o[j]       = __float2half(x0 * c - x1 * sn);
            o[j + 128] = __float2half(x1 * c + x0 * sn);
        }
    } else {
        // ---- V transpose part: blocks 2048..6143 ----
        __shared__ __half t[32][40];
        int vb = blockIdx.x - 2048;
        int s0 = (vb & 127) * 32;
        int d0 = ((vb >> 7) & 7) * 32;
        int kvh = vb >> 10;
        int tid = threadIdx.x;
        int tx = tid & 31, ty = tid >> 5;
        #pragma unroll
        for (int i = 0; i < 4; i++)
            t[ty + 8 * i][tx] =
                g_qkv16[(size_t)(s0 + ty + 8 * i) * NQKV + 3072 + kvh * HD + d0 + tx];
        __syncthreads();
        #pragma unroll
        for (int i = 0; i < 4; i++) {
            int d = ty + 8 * i, s = tx;
            g_vt[(size_t)kvh * HD * SQ + (size_t)(d0 + d) * SQ + s0 + s] = t[s][d];
        }
    }
}

// ================= fp16 HMMA flash attention, double-buffered K/V (R13) =================
#define ABM 128
#define ABN 64
#define QROWH 264
#define VROWH 72
#define KSTAGE (ABN * QROWH * 2)
#define VSTAGE (HD * VROWH * 2)
#define ASM_K (ABM * QROWH * 2)
#define ASM_V (ASM_K + 2 * KSTAGE)
#define ASM_MK (ASM_V + 2 * VSTAGE)
#define ATTN_SMEM (ASM_MK + 2 * ABN * 4)

__global__ __launch_bounds__(256, 1) void attn_mma_kernel(const int* __restrict__ amask) {
    extern __shared__ __align__(128) char asmem[];
    const uint32_t sb = smem_u32(asmem);
    const int tid = threadIdx.x;
    const int lane = tid & 31;
    const int w = tid >> 5;
    const int bx = gridDim.x - 1 - blockIdx.x;
    const int h = blockIdx.y;
    const int kvh = h >> 1;
    const int m0 = bx * ABM;
    const int wrow = w * 16;
    const int rq = lane >> 2;
    const int q2 = (lane & 3) * 2;

    const __half* gQ = g_qh + ((size_t)h * SQ + m0) * HD;
    const __half* gK = g_kh + (size_t)kvh * SQ * HD;
    const __half* gVt = g_vt + (size_t)kvh * HD * SQ;

    for (int c = tid; c < ABM * 32; c += 256) {
        int r = c >> 5, g = c & 31;
        cpasync16(sb + (uint32_t)(r * (QROWH * 2) + g * 16),
                  (const char*)(gQ + (size_t)r * HD) + g * 16);
    }
    cp_commit();

    float accO[32][4];
    #pragma unroll
    for (int vt = 0; vt < 32; vt++)
        #pragma unroll
        for (int e = 0; e < 4; e++) accO[vt][e] = 0.f;
    float mprev0 = -1e30f, mprev1 = -1e30f;
    float lsum0 = 0.f, lsum1 = 0.f;

    const uint32_t aQ = sb + (uint32_t)((wrow + (lane & 15)) * (QROWH * 2) + ((lane >> 4) * 8) * 2);
    const uint32_t bKoff = (uint32_t)((lane & 7) * (QROWH * 2) + (((lane >> 3) & 1) * 8) * 2);
    const uint32_t bVoff = (uint32_t)((lane & 7) * (VROWH * 2) + (((lane >> 3) & 1) * 8) * 2);

    const int ntiles = 2 * bx + 2;

    {
        for (int c = tid; c < ABN * 32; c += 256) {
            int r = c >> 5, g = c & 31;
            cpasync16(sb + (uint32_t)(ASM_K + r * (QROWH * 2) + g * 16),
                      (const char*)(gK + (size_t)r * HD) + g * 16);
        }
        for (int c = tid; c < HD * 8; c += 256) {
            int r = c >> 3, g = c & 7;
            cpasync16(sb + (uint32_t)(ASM_V + r * (VROWH * 2) + g * 16),
                      (const char*)(gVt + (size_t)r * SQ) + g * 16);
        }
        if (tid < ABN) ((float*)(asmem + ASM_MK))[tid] = (amask[tid] > 0) ? 0.f : -1e30f;
        cp_commit();
    }

    for (int jt = 0; jt < ntiles; jt++) {
        const int cur = jt & 1;
        if (jt + 1 < ntiles) {
            const int nxt = (jt + 1) & 1;
            const int n1 = (jt + 1) * ABN;
            for (int c = tid; c < ABN * 32; c += 256) {
                int r = c >> 5, g = c & 31;
                cpasync16(sb + (uint32_t)(ASM_K + nxt * KSTAGE + r * (QROWH * 2) + g * 16),
                          (const char*)(gK + (size_t)(n1 + r) * HD) + g * 16);
            }
            for (int c = tid; c < HD * 8; c += 256) {
                int r = c >> 3, g = c & 7;
                cpasync16(sb + (uint32_t)(ASM_V + nxt * VSTAGE + r * (VROWH * 2) + g * 16),
                          (const char*)(gVt + (size_t)r * SQ + n1) + g * 16);
            }
            if (tid < ABN)
                ((float*)(asmem + ASM_MK))[nxt * ABN + tid] =
                    (amask[n1 + tid] > 0) ? 0.f : -1e30f;
            cp_commit();
            cp_wait<1>();
        } else {
            cp_wait<0>();
        }
        __syncthreads();

        const int n0 = jt * ABN;
        if (n0 <= m0 + wrow + 15) {
            const float* mk = (const float*)(asmem + ASM_MK) + cur * ABN;
            const uint32_t bK = sb + (uint32_t)(ASM_K + cur * KSTAGE) + bKoff;
            const uint32_t bV = sb + (uint32_t)(ASM_V + cur * VSTAGE) + bVoff;

            float accS[8][4];
            #pragma unroll
            for (int nt = 0; nt < 8; nt++)
                #pragma unroll
                for (int e = 0; e < 4; e++) accS[nt][e] = 0.f;
            #pragma unroll
            for (int kc = 0; kc < 16; kc++) {
                uint32_t a[4];
                ldsm4(a, aQ + kc * 32);
                #pragma unroll
                for (int nt = 0; nt < 8; nt++) {
                    uint32_t b[2];
                    ldsm2(b, bK + nt * (8 * QROWH * 2) + kc * 32);
                    mma16816(accS[nt], a, b);
                }
            }

            const int grow0 = m0 + wrow + rq;
            const int grow1 = grow0 + 8;
            #pragma unroll
            for (int nt = 0; nt < 8; nt++) {
                int c0 = nt * 8 + q2;
                float k0m = mk[c0], k1m = mk[c0 + 1];
                int gc0 = n0 + c0, gc1 = gc0 + 1;
                accS[nt][0] = (gc0 > grow0) ? -1e30f : accS[nt][0] + k0m;
                accS[nt][1] = (gc1 > grow0) ? -1e30f : accS[nt][1] + k1m;
                accS[nt][2] = (gc0 > grow1) ? -1e30f : accS[nt][2] + k0m;
                accS[nt][3] = (gc1 > grow1) ? -1e30f : accS[nt][3] + k1m;
            }

            float mx0 = -1e30f, mx1 = -1e30f;
            #pragma unroll
            for (int nt = 0; nt < 8; nt++) {
                mx0 = fmaxf(mx0, fmaxf(accS[nt][0], accS[nt][1]));
                mx1 = fmaxf(mx1, fmaxf(accS[nt][2], accS[nt][3]));
            }
            mx0 = fmaxf(mx0, __shfl_xor_sync(0xffffffffu, mx0, 1));
            mx0 = fmaxf(mx0, __shfl_xor_sync(0xffffffffu, mx0, 2));
            mx1 = fmaxf(mx1, __shfl_xor_sync(0xffffffffu, mx1, 1));
            mx1 = fmaxf(mx1, __shfl_xor_sync(0xffffffffu, mx1, 2));
            float nm0 = fmaxf(mprev0, mx0);
            float nm1 = fmaxf(mprev1, mx1);
            float sc0 = __expf(mprev0 - nm0);
            float sc1 = __expf(mprev1 - nm1);
            float s0 = 0.f, s1 = 0.f;
            #pragma unroll
            for (int nt = 0; nt < 8; nt++) {
                float p0 = __expf(accS[nt][0] - nm0);
                float p1 = __expf(accS[nt][1] - nm0);
                float p2 = __expf(accS[nt][2] - nm1);
                float p3 = __expf(accS[nt][3] - nm1);
                accS[nt][0] = p0; accS[nt][1] = p1; accS[nt][2] = p2; accS[nt][3] = p3;
                s0 += p0 + p1; s1 += p2 + p3;
            }
            s0 += __shfl_xor_sync(0xffffffffu, s0, 1);
            s0 += __shfl_xor_sync(0xffffffffu, s0, 2);
            s1 += __shfl_xor_sync(0xffffffffu, s1, 1);
            s1 += __shfl_xor_sync(0xffffffffu, s1, 2);
            lsum0 = lsum0 * sc0 + s0;
            lsum1 = lsum1 * sc1 + s1;
            mprev0 = nm0; mprev1 = nm1;
            #pragma unroll
            for (int vt = 0; vt < 32; vt++) {
                accO[vt][0] *= sc0; accO[vt][1] *= sc0;
                accO[vt][2] *= sc1; accO[vt][3] *= sc1;
            }

            #pragma unroll
            for (int kc2 = 0; kc2 < 4; kc2++) {
                uint32_t a[4];
                a[0] = packh2(accS[2 * kc2][0], accS[2 * kc2][1]);
                a[1] = packh2(accS[2 * kc2][2], accS[2 * kc2][3]);
                a[2] = packh2(accS[2 * kc2 + 1][0], accS[2 * kc2 + 1][1]);
                a[3] = packh2(accS[2 * kc2 + 1][2], accS[2 * kc2 + 1][3]);
                #pragma unroll
                for (int vt = 0; vt < 32; vt++) {
                    uint32_t b[2];
                    ldsm2(b, bV + vt * (8 * VROWH * 2) + kc2 * 32);
                    mma16816(accO[vt], a, b);
                }
            }
        }
        __syncthreads();
    }

    float il0 = 1.f / lsum0;
    float il1 = 1.f / lsum1;
    __half* o0 = g_attn + (size_t)(m0 + wrow + rq) * HID + h * HD;
    __half* o1 = g_attn + (size_t)(m0 + wrow + rq + 8) * HID + h * HD;
    #pragma unroll
    for (int vt = 0; vt < 32; vt++) {
        int c = vt * 8 + q2;
        *(__half2*)(o0 + c) = __floats2half2_rn(accO[vt][0] * il0, accO[vt][1] * il0);
        *(__half2*)(o1 + c) = __floats2half2_rn(accO[vt][2] * il1, accO[vt][3] * il1);
    }
}

// ================= launch =================
template <typename T>
static T* symaddr(const void* sym) {
    void* p = nullptr;
    cudaGetSymbolAddress(&p, sym);
    return (T*)p;
}

extern "C" void kernel_launch(void* const* d_in, const int* in_sizes, int n_in,
                              void* d_out, int out_size) {
    (void)in_sizes; (void)n_in; (void)out_size;
    const float* hs     = (const float*)d_in[0];
    const float* q_w    = (const float*)d_in[1];
    const float* k_w    = (const float*)d_in[2];
    const float* v_w    = (const float*)d_in[3];
    const float* o_w    = (const float*)d_in[4];
    const float* gate_w = (const float*)d_in[5];
    const float* up_w   = (const float*)d_in[6];
    const float* down_w = (const float*)d_in[7];
    const float* ln1_w  = (const float*)d_in[8];
    const float* ln2_w  = (const float*)d_in[9];
    const int*   amask  = (const int*)d_in[10];
    const int*   pos    = (const int*)d_in[11];
    float* out = (float*)d_out;

    __half* xn = symaddr<__half>(g_xn);
    __half* qkv16 = symaddr<__half>(g_qkv16);
    __half* at = symaddr<__half>(g_attn);
    float* h1 = symaddr<float>(g_h1);
    __half* ga = symaddr<__half>(g_gact);
    __half* qkvw = symaddr<__half>(g_qkvw);
    __half* ow = symaddr<__half>(g_ow);
    __half* gw = symaddr<__half>(g_gw);
    __half* uw = symaddr<__half>(g_uw);
    __half* dw = symaddr<__half>(g_dw);

    cudaFuncSetAttribute(mma_gemm_kernel, cudaFuncAttributeMaxDynamicSharedMemorySize, GEMM_SMEM);
    cudaFuncSetAttribute(gateup_kernel, cudaFuncAttributeMaxDynamicSharedMemorySize, GU_SMEM);
    cudaFuncSetAttribute(attn_mma_kernel, cudaFuncAttributeMaxDynamicSharedMemorySize, ATTN_SMEM);

    // 0) batched weight transpose (one launch)
    WJobs jb;
    jb.W[0] = q_w;    jb.T[0] = qkvw;                       jb.K[0] = HID; jb.N[0] = 2048;
    jb.W[1] = k_w;    jb.T[1] = qkvw + (size_t)2048 * HID;  jb.K[1] = HID; jb.N[1] = 1024;
    jb.W[2] = v_w;    jb.T[2] = qkvw + (size_t)3072 * HID;  jb.K[2] = HID; jb.N[2] = 1024;
    jb.W[3] = o_w;    jb.T[3] = ow;                         jb.K[3] = HID; jb.N[3] = 2048;
    jb.W[4] = gate_w; jb.T[4] = gw;                         jb.K[4] = HID; jb.N[4] = FFI;
    jb.W[5] = up_w;   jb.T[5] = uw;                         jb.K[5] = HID; jb.N[5] = FFI;
    jb.W[6] = down_w; jb.T[6] = dw;                         jb.K[6] = FFI; jb.N[6] = HID;
    int off = 0;
    for (int i = 0; i < 7; i++) {
        jb.ntilesX[i] = jb.N[i] / 64;
        jb.tileOff[i] = off;
        off += (jb.K[i] / 64) * (jb.N[i] / 64);
    }
    jb.tileOff[7] = off;
    wconv_all_kernel<<<off, 256>>>(jb);

    // 1) input RMSNorm -> fp16
    rmsnorm_kernel<<<SQ, 256>>>(hs, ln1_w, xn);

    // 2) fused QKV projection (fp16 out)
    mma_gemm_kernel<<<dim3(SQ / 128, NQKV / 128), 256, GEMM_SMEM>>>(
        xn, qkvw, nullptr, nullptr, qkv16, NQKV, HID);

    // 3) RoPE + V transpose (one launch)
    rope_vtrans_kernel<<<2048 + 4096, 256>>>(pos);

    // 4) flash attention (double-buffered)
    attn_mma_kernel<<<dim3(SQ / ABM, NH), 256, ATTN_SMEM>>>(amask);

    // 5) O projection + residual (fp32 out)
    mma_gemm_kernel<<<dim3(SQ / 128, HID / 128), 256, GEMM_SMEM>>>(
        at, ow, hs, h1, nullptr, HID, HID);

    // 6) post-attn RMSNorm -> fp16
    rmsnorm_kernel<<<SQ, 256>>>(h1, ln2_w, xn);

    // 7) MLP
    gateup_kernel<<<dim3(SQ / 128, FFI / 128), 256, GU_SMEM>>>(xn, gw, uw, ga, FFI, HID);
    mma_gemm_kernel<<<dim3(SQ / 128, HID / 128), 256, GEMM_SMEM>>>(
        ga, dw, h1, out, nullptr, HID, FFI);
}